// round 7
// baseline (speedup 1.0000x reference)
#include <cuda_runtime.h>
#include <cstdint>

// ---------------------------------------------------------------- constants
#define Bn 4096
#define Vn 256
#define Hn 64
#define SROW (257 * 256)        // floats per batch element of `state`

#define NTH   256               // 8 warps
#define NSTG  3                 // A pipeline stages
#define MROWS 512               // rows per block (= 2 batch elements)
#define NBLK  (Bn / 2)          // 2048 blocks
#define KCH   16                // k per chunk
#define NCHK  (256 / KCH)       // 16 chunks per block

#define ASTRIDE 20              // A smem row stride (20*g+t mod 32 all distinct)
#define BSTRIDE 72              // B smem row stride (72 % 32 == 8 -> conflict-free)
#define ASTF (MROWS * ASTRIDE)  // floats per A stage (10240 = 40KB)
// smem: A[3][10240] + B[256*72] + bias[64] + w2[64]
#define SMEM_FLOATS (NSTG * ASTF + 256 * BSTRIDE + 128)
#define SMEM_BYTES  (SMEM_FLOATS * 4)   // 197120

// ---------------------------------------------------------------- scratch
__device__ float g_pm[64 * Vn];
__device__ float g_ps[64 * Vn];
__device__ float g_colM[Vn];
__device__ float g_colS[Vn];

// ---------------------------------------------------------------- helpers
__device__ __forceinline__ uint32_t smem_u32(const void* p) {
    uint32_t a;
    asm("{ .reg .u64 t; cvta.to.shared.u64 t, %1; cvt.u32.u64 %0, t; }"
        : "=r"(a) : "l"(p));
    return a;
}
__device__ __forceinline__ void cpa16(uint32_t dst, const void* src) {
    asm volatile("cp.async.cg.shared.global [%0], [%1], 16;" :: "r"(dst), "l"(src));
}
#define CPA_COMMIT() asm volatile("cp.async.commit_group;" ::: "memory")

__device__ __forceinline__ uint32_t totf32(float x) {
    uint32_t r;
    asm("cvt.rna.tf32.f32 %0, %1;" : "=r"(r) : "f"(x));
    return r;
}
__device__ __forceinline__ void mma_tf32(float* d, const uint32_t* a,
                                         uint32_t b0, uint32_t b1) {
    asm volatile(
        "mma.sync.aligned.m16n8k8.row.col.f32.tf32.tf32.f32 "
        "{%0,%1,%2,%3}, {%4,%5,%6,%7}, {%8,%9}, {%0,%1,%2,%3};"
        : "+f"(d[0]), "+f"(d[1]), "+f"(d[2]), "+f"(d[3])
        : "r"(a[0]), "r"(a[1]), "r"(a[2]), "r"(a[3]), "r"(b0), "r"(b1));
}

// issue one 512-row x 16-k A chunk into stage `stg` via cp.async (one group)
// rows span 2 batches: row r -> batch 2*blk + (r>>8), v = r&255
__device__ __forceinline__ void issue_chunk(const float* __restrict__ state,
                                            uint32_t sA_u32, int blk, int c,
                                            int stg, int tid) {
    const int kq = tid & 3;         // 16B granule within 16-float k-chunk
    const int r0 = tid >> 2;        // 0..63 base row
    const uint32_t dst0 = sA_u32 + (uint32_t)(stg * ASTF + r0 * ASTRIDE + kq * 4) * 4u;
    #pragma unroll
    for (int i = 0; i < 8; i++) {   // rows r0 + 64*i (0..511)
        const int r = r0 + 64 * i;
        const int batch = 2 * blk + (r >> 8);
        const int v = r & 255;
        const float* src = state + (size_t)batch * SROW + (size_t)(v + 1) * 256
                         + c * KCH + kq * 4;
        cpa16(dst0 + (uint32_t)(64 * i * ASTRIDE) * 4u, src);
    }
    CPA_COMMIT();
}

// ---------------------------------------------------------------- K1
// q[b*256+v] = sum_h relu( dist[b,v,:].W1[:,h] + vis[b,v]*b_vis[h] ) * w2[h]
// Persistent CTA; block = 2 batches (512 rows). Warp tile: 64 rows x 64 h.
__global__ __launch_bounds__(NTH, 1)
void k1_gemm(const float* __restrict__ state, const float* __restrict__ W1,
             const float* __restrict__ b_vis, const float* __restrict__ w2,
             float* __restrict__ qout)
{
    extern __shared__ __align__(16) float sm[];
    float* sA    = sm;
    float* sB    = sm + NSTG * ASTF;
    float* sBias = sB + 256 * BSTRIDE;
    float* sW2   = sBias + 64;
    const uint32_t sA_u32 = smem_u32(sA);

    const int tid  = threadIdx.x;
    const int lane = tid & 31;
    const int warp = tid >> 5;
    const int bx   = blockIdx.x;
    const int G    = gridDim.x;

    const int nblk = (NBLK - bx + G - 1) / G;
    const int NCC  = nblk * NCHK;            // chunks (16 per block)

    // prefetch chunk 0 while staging B
    issue_chunk(state, sA_u32, bx, 0, 0, tid);

    // stage B = W1 [256 k][64 h], tf32-rounded, stride 72
    #pragma unroll
    for (int i = 0; i < 16; i++) {
        const int idx  = tid + 256 * i;      // float4 index 0..4095
        const int kr   = idx >> 4;
        const int quad = idx & 15;
        const float4 v = ((const float4*)W1)[idx];
        float* dst = sB + kr * BSTRIDE + quad * 4;
        dst[0] = __uint_as_float(totf32(v.x));
        dst[1] = __uint_as_float(totf32(v.y));
        dst[2] = __uint_as_float(totf32(v.z));
        dst[3] = __uint_as_float(totf32(v.w));
    }
    if (tid < 64)        sBias[tid]     = b_vis[tid];
    else if (tid < 128)  sW2[tid - 64]  = w2[tid - 64];
    __syncthreads();

    float d[4][8][4];                        // [m16 group][j (n8)][frag]

    for (int cc = 0; cc < NCC; cc++) {
        const int blk = bx + (cc >> 4) * G;
        const int c   = cc & 15;

        if (cc + 1 < NCC) {
            const int cc1 = cc + 1;
            issue_chunk(state, sA_u32, bx + (cc1 >> 4) * G, cc1 & 15,
                        cc1 % 3, tid);
            asm volatile("cp.async.wait_group 1;" ::: "memory");
        } else {
            asm volatile("cp.async.wait_group 0;" ::: "memory");
        }
        __syncthreads();   // chunk cc visible; 3-stage rotation race-free

        if (c == 0) {
            #pragma unroll
            for (int g = 0; g < 4; g++)
                #pragma unroll
                for (int j = 0; j < 8; j++)
                    #pragma unroll
                    for (int e = 0; e < 4; e++) d[g][j][e] = 0.f;
        }

        const float* As = sA + (cc % 3) * ASTF;
        #pragma unroll
        for (int ks = 0; ks < 2; ks++) {
            const int k0 = ks * 8;
            const int kg = c * KCH + k0;

            uint32_t a[4][4];
            #pragma unroll
            for (int g = 0; g < 4; g++) {
                const float* ap = As + (warp * 64 + g * 16 + (lane >> 2)) * ASTRIDE
                                + k0 + (lane & 3);
                a[g][0] = totf32(ap[0]);
                a[g][1] = totf32(ap[8 * ASTRIDE]);
                a[g][2] = totf32(ap[4]);
                a[g][3] = totf32(ap[8 * ASTRIDE + 4]);
            }
            #pragma unroll
            for (int j = 0; j < 8; j++) {
                const float* bp = sB + (kg + (lane & 3)) * BSTRIDE
                                + j * 8 + (lane >> 2);
                const uint32_t b0 = __float_as_uint(bp[0]);
                const uint32_t b1 = __float_as_uint(bp[4 * BSTRIDE]);
                mma_tf32(d[0][j], a[0], b0, b1);
                mma_tf32(d[1][j], a[1], b0, b1);
                mma_tf32(d[2][j], a[2], b0, b1);
                mma_tf32(d[3][j], a[3], b0, b1);
            }
        }

        if (c == 15) {
            // fused epilogue: relu(acc + vis*bias)*w2, reduce over h
            #pragma unroll
            for (int g = 0; g < 4; g++) {
                #pragma unroll
                for (int half = 0; half < 2; half++) {
                    const int r = warp * 64 + g * 16 + (lane >> 2) + half * 8;
                    const int batch = 2 * blk + (r >> 8);
                    const int v = r & 255;
                    const float vis = __ldg(state + (size_t)batch * SROW + v);
                    float p = 0.f;
                    #pragma unroll
                    for (int j = 0; j < 8; j++) {
                        const int n = j * 8 + (lane & 3) * 2;
                        p += fmaxf(fmaf(vis, sBias[n],     d[g][j][half * 2]),     0.f) * sW2[n];
                        p += fmaxf(fmaf(vis, sBias[n + 1], d[g][j][half * 2 + 1]), 0.f) * sW2[n + 1];
                    }
                    p += __shfl_xor_sync(0xffffffffu, p, 1);
                    p += __shfl_xor_sync(0xffffffffu, p, 2);
                    if ((lane & 3) == 0)
                        qout[(size_t)blk * MROWS + r] = p;
                }
            }
        }
    }
}

// ---------------------------------------------------------------- K2: column softmax stats
__global__ __launch_bounds__(256) void k2_colpart(const float* __restrict__ q)
{
    const int t  = threadIdx.x;
    const int r0 = blockIdx.x * 64;
    float m = -3.402823466e38f, s = 0.f;
    const float* p = q + (size_t)r0 * Vn + t;
    #pragma unroll 4
    for (int i = 0; i < 64; i++) {
        const float x  = p[(size_t)i * Vn];
        const float nm = fmaxf(m, x);
        s = s * __expf(m - nm) + __expf(x - nm);
        m = nm;
    }
    g_pm[blockIdx.x * Vn + t] = m;
    g_ps[blockIdx.x * Vn + t] = s;
}

__global__ __launch_bounds__(256) void k2_colcomb()
{
    const int t = threadIdx.x;
    float M = -3.402823466e38f;
    #pragma unroll 8
    for (int i = 0; i < 64; i++) M = fmaxf(M, g_pm[i * Vn + t]);
    float S = 0.f;
    #pragma unroll 8
    for (int i = 0; i < 64; i++) S += g_ps[i * Vn + t] * __expf(g_pm[i * Vn + t] - M);
    g_colM[t] = M;
    g_colS[t] = S;
}

// ---------------------------------------------------------------- K3: policy + value
__global__ __launch_bounds__(256) void k3_final(
    const float* __restrict__ q, const float* __restrict__ state,
    const float* __restrict__ Wv, const float* __restrict__ bv,
    float* __restrict__ policy, float* __restrict__ value)
{
    __shared__ float sred[16];
    __shared__ float sbc;

    const int b = blockIdx.x;
    const int v = threadIdx.x;

    const float x   = q[(size_t)b * Vn + v];
    const float vis = state[(size_t)b * SROW + v];

    float tempv = __expf(x - g_colM[v]) / g_colS[v] + 0.01f;
    tempv = (vis == 0.0f) ? tempv : 0.0f;   // masked terms exact zeros
    const float vp = x * Wv[v];

    float s1 = tempv, s2 = vp;
    #pragma unroll
    for (int off = 16; off >= 1; off >>= 1) {
        s1 += __shfl_xor_sync(0xffffffffu, s1, off);
        s2 += __shfl_xor_sync(0xffffffffu, s2, off);
    }
    const int lane = v & 31, w = v >> 5;
    if (lane == 0) { sred[w] = s1; sred[8 + w] = s2; }
    __syncthreads();
    if (v == 0) {
        float rs = 0.f, vv = 0.f;
        #pragma unroll
        for (int i = 0; i < 8; i++) { rs += sred[i]; vv += sred[8 + i]; }
        sbc = rs;
        value[b] = vv + bv[0];
    }
    __syncthreads();
    const float rowsum = sbc;

    float pol;
    if (rowsum == 0.0f) pol = (v == 0) ? 1.0f : 0.0f;
    else                pol = tempv / rowsum;
    policy[(size_t)b * Vn + v] = pol;
}

// ---------------------------------------------------------------- launch
extern "C" void kernel_launch(void* const* d_in, const int* in_sizes, int n_in,
                              void* d_out, int out_size)
{
    const float* state = (const float*)d_in[0];
    const float* W1    = (const float*)d_in[1];
    const float* b_vis = (const float*)d_in[2];
    const float* w2    = (const float*)d_in[3];
    const float* Wv    = (const float*)d_in[4];
    const float* bv    = (const float*)d_in[5];

    float* out    = (float*)d_out;
    float* q      = out;
    float* policy = out + (size_t)Bn * Vn;
    float* value  = out + (size_t)2 * Bn * Vn;

    // persistent grid = #SMs (GB300=152, B300=148); host-side query is
    // capture-legal and runs only at capture time, not on replay.
    int nsm = 148;
    cudaDeviceGetAttribute(&nsm, cudaDevAttrMultiProcessorCount, 0);
    if (nsm <= 0 || nsm > NBLK) nsm = 148;

    cudaFuncSetAttribute(k1_gemm, cudaFuncAttributeMaxDynamicSharedMemorySize,
                         SMEM_BYTES);

    k1_gemm<<<nsm, NTH, SMEM_BYTES>>>(state, W1, b_vis, w2, q);
    k2_colpart<<<64, 256>>>(q);
    k2_colcomb<<<1, 256>>>();
    k3_final<<<Bn, 256>>>(q, state, Wv, bv, policy, value);
}

// round 12
// speedup vs baseline: 1.2531x; 1.2531x over previous
#include <cuda_runtime.h>
#include <cuda_fp16.h>
#include <cstdint>

// ---------------------------------------------------------------- constants
#define Bn 4096
#define Vn 256
#define Hn 64
#define SROW (257 * 256)        // floats per batch element of `state`

#define NTH  256                // 8 warps
#define NSTG 4                  // A pipeline stages
#define NCHK 8                  // 8 chunks of 32 k per block (block = 1 batch)

#define ASTRIDE 40              // A row stride (G*8+2t distinct per 16-lane phase)
#define BPITCH  264             // B fp16 [n][k] pitch in halves (4g+t distinct banks)
#define ASTF (256 * ASTRIDE)    // floats per A stage (10240 = 40KB)

// smem: A[4][10240] f32 + B 64x264 f16 (8448 f32-equiv) + bias 64 + w2 64
#define SMEM_FLOATS (NSTG * ASTF + 8448 + 128)
#define SMEM_BYTES  (SMEM_FLOATS * 4)   // 198144

// ---------------------------------------------------------------- scratch
__device__ float g_pm[64 * Vn];
__device__ float g_ps[64 * Vn];
__device__ float g_colM[Vn];
__device__ float g_colS[Vn];

// ---------------------------------------------------------------- helpers
__device__ __forceinline__ uint32_t smem_u32(const void* p) {
    uint32_t a;
    asm("{ .reg .u64 t; cvta.to.shared.u64 t, %1; cvt.u32.u64 %0, t; }"
        : "=r"(a) : "l"(p));
    return a;
}
__device__ __forceinline__ void cpa16(uint32_t dst, const void* src) {
    asm volatile("cp.async.cg.shared.global [%0], [%1], 16;" :: "r"(dst), "l"(src));
}
#define CPA_COMMIT() asm volatile("cp.async.commit_group;" ::: "memory")

__device__ __forceinline__ uint32_t packh2(float x, float y) {
    const __half2 h = __floats2half2_rn(x, y);   // x -> low half
    return *(const uint32_t*)&h;
}
__device__ __forceinline__ void mma_f16(float* d, const uint32_t* a,
                                        uint32_t b0, uint32_t b1) {
    asm volatile(
        "mma.sync.aligned.m16n8k16.row.col.f32.f16.f16.f32 "
        "{%0,%1,%2,%3}, {%4,%5,%6,%7}, {%8,%9}, {%0,%1,%2,%3};"
        : "+f"(d[0]), "+f"(d[1]), "+f"(d[2]), "+f"(d[3])
        : "r"(a[0]), "r"(a[1]), "r"(a[2]), "r"(a[3]), "r"(b0), "r"(b1));
}

// issue one 256-row x 32-k A chunk into stage `stg` via cp.async (one group)
__device__ __forceinline__ void issue_chunk(const float* __restrict__ state,
                                            uint32_t sA_u32, int blk, int c,
                                            int stg, int tid) {
    const int kv = tid & 7;         // 16B granule within 32-float k-chunk
    const int r0 = tid >> 3;        // 0..31 base row
    const float* src = state + (size_t)blk * SROW + (size_t)(r0 + 1) * 256
                     + c * 32 + kv * 4;
    uint32_t dst = sA_u32 + (uint32_t)(stg * ASTF + r0 * ASTRIDE + kv * 4) * 4u;
    #pragma unroll
    for (int i = 0; i < 8; i++) {   // rows r0 + 32*i
        cpa16(dst, src);
        dst += 32 * ASTRIDE * 4;
        src += 32 * 256;
    }
    CPA_COMMIT();
}

// ---------------------------------------------------------------- K1
// q[b*256+v] = sum_h relu( dist[b,v,:].W1[:,h] + vis[b,v]*b_vis[h] ) * w2[h]
// Persistent CTA; block = one batch (256 rows). Warp tile 32 rows x 64 h.
// fp16 m16n8k16 MMA, fp32 accumulate.
__global__ __launch_bounds__(NTH, 1)
void k1_gemm(const float* __restrict__ state, const float* __restrict__ W1,
             const float* __restrict__ b_vis, const float* __restrict__ w2,
             float* __restrict__ qout)
{
    extern __shared__ __align__(16) float sm[];
    float*  sA    = sm;
    __half* sB16  = (__half*)(sm + NSTG * ASTF);      // [64][BPITCH] halves
    float*  sBias = sm + NSTG * ASTF + 8448;
    float*  sW2   = sBias + 64;
    const uint32_t sA_u32 = smem_u32(sA);

    const int tid  = threadIdx.x;
    const int lane = tid & 31;
    const int warp = tid >> 5;
    const int bx   = blockIdx.x;
    const int G    = gridDim.x;

    const int nblk = (Bn - bx + G - 1) / G;
    const int NCC  = nblk * NCHK;

    // prefetch chunk 0 while staging B
    issue_chunk(state, sA_u32, bx, 0, 0, tid);

    // stage B = W1 [256 k][64 h] -> fp16 transposed [h][k], pitch 264
    #pragma unroll
    for (int i = 0; i < 16; i++) {
        const int idx  = tid + 256 * i;      // float4 index 0..4095 over W1
        const int kr   = idx >> 4;           // k row
        const int quad = idx & 15;           // h group of 4
        const float4 v = ((const float4*)W1)[idx];
        __half* dst = sB16 + (quad * 4) * BPITCH + kr;
        dst[0]          = __float2half_rn(v.x);
        dst[BPITCH]     = __float2half_rn(v.y);
        dst[2 * BPITCH] = __float2half_rn(v.z);
        dst[3 * BPITCH] = __float2half_rn(v.w);
    }
    if (tid < 64)        sBias[tid]    = b_vis[tid];
    else if (tid < 128)  sW2[tid - 64] = w2[tid - 64];
    __syncthreads();

    const int gq = lane >> 2;       // groupID 0..7
    const int t2 = (lane & 3) * 2;

    float d[2][8][4];

    for (int cc = 0; cc < NCC; cc++) {
        const int blk = bx + (cc >> 3) * G;
        const int c   = cc & 7;

        if (cc + 1 < NCC) {
            const int cc1 = cc + 1;
            issue_chunk(state, sA_u32, bx + (cc1 >> 3) * G, cc1 & 7,
                        cc1 & 3, tid);
            asm volatile("cp.async.wait_group 1;" ::: "memory");
        } else {
            asm volatile("cp.async.wait_group 0;" ::: "memory");
        }
        __syncthreads();   // chunk cc visible; 4-stage rotation race-free

        if (c == 0) {
            #pragma unroll
            for (int g = 0; g < 2; g++)
                #pragma unroll
                for (int j = 0; j < 8; j++)
                    #pragma unroll
                    for (int e = 0; e < 4; e++) d[g][j][e] = 0.f;
        }

        const float* As = sA + (cc & 3) * ASTF;
        #pragma unroll
        for (int ks = 0; ks < 2; ks++) {
            const int k0 = ks * 16;
            const int kg = c * 32 + k0;

            uint32_t a[2][4];
            #pragma unroll
            for (int g = 0; g < 2; g++) {
                const float* ap = As + (warp * 32 + g * 16 + gq) * ASTRIDE
                                + k0 + t2;
                const float2 v0 = *(const float2*)(ap);
                const float2 v1 = *(const float2*)(ap + 8 * ASTRIDE);
                const float2 v2 = *(const float2*)(ap + 8);
                const float2 v3 = *(const float2*)(ap + 8 * ASTRIDE + 8);
                a[g][0] = packh2(v0.x, v0.y);
                a[g][1] = packh2(v1.x, v1.y);
                a[g][2] = packh2(v2.x, v2.y);
                a[g][3] = packh2(v3.x, v3.y);
            }
            #pragma unroll
            for (int j = 0; j < 8; j++) {
                const __half* bp = sB16 + (j * 8 + gq) * BPITCH + kg + t2;
                const uint32_t b0 = *(const uint32_t*)(bp);
                const uint32_t b1 = *(const uint32_t*)(bp + 8);
                mma_f16(d[0][j], a[0], b0, b1);
                mma_f16(d[1][j], a[1], b0, b1);
            }
        }

        if (c == 7) {
            // fused epilogue: relu(acc + vis*bias)*w2, reduce over h
            #pragma unroll
            for (int g = 0; g < 2; g++) {
                #pragma unroll
                for (int half = 0; half < 2; half++) {
                    const int r = warp * 32 + g * 16 + gq + half * 8;
                    const float vis = __ldg(state + (size_t)blk * SROW + r);
                    float p = 0.f;
                    #pragma unroll
                    for (int j = 0; j < 8; j++) {
                        const int n = j * 8 + t2;
                        p += fmaxf(fmaf(vis, sBias[n],     d[g][j][half * 2]),     0.f) * sW2[n];
                        p += fmaxf(fmaf(vis, sBias[n + 1], d[g][j][half * 2 + 1]), 0.f) * sW2[n + 1];
                    }
                    p += __shfl_xor_sync(0xffffffffu, p, 1);
                    p += __shfl_xor_sync(0xffffffffu, p, 2);
                    if ((lane & 3) == 0)
                        qout[(size_t)blk * 256 + r] = p;
                }
            }
        }
    }
}

// ---------------------------------------------------------------- K2: column softmax stats
__global__ __launch_bounds__(256) void k2_colpart(const float* __restrict__ q)
{
    const int t  = threadIdx.x;
    const int r0 = blockIdx.x * 64;
    float m = -3.402823466e38f, s = 0.f;
    const float* p = q + (size_t)r0 * Vn + t;
    #pragma unroll 4
    for (int i = 0; i < 64; i++) {
        const float x  = p[(size_t)i * Vn];
        const float nm = fmaxf(m, x);
        s = s * __expf(m - nm) + __expf(x - nm);
        m = nm;
    }
    g_pm[blockIdx.x * Vn + t] = m;
    g_ps[blockIdx.x * Vn + t] = s;
}

__global__ __launch_bounds__(256) void k2_colcomb()
{
    const int t = threadIdx.x;
    float M = -3.402823466e38f;
    #pragma unroll 8
    for (int i = 0; i < 64; i++) M = fmaxf(M, g_pm[i * Vn + t]);
    float S = 0.f;
    #pragma unroll 8
    for (int i = 0; i < 64; i++) S += g_ps[i * Vn + t] * __expf(g_pm[i * Vn + t] - M);
    g_colM[t] = M;
    g_colS[t] = S;
}

// ---------------------------------------------------------------- K3: policy + value
// warp-per-batch: no smem, no block syncs. 8 warps/block, grid = Bn/8.
__global__ __launch_bounds__(256) void k3_final(
    const float* __restrict__ q, const float* __restrict__ state,
    const float* __restrict__ Wv, const float* __restrict__ bv,
    float* __restrict__ policy, float* __restrict__ value)
{
    const int lane = threadIdx.x & 31;
    const int b    = blockIdx.x * 8 + (threadIdx.x >> 5);

    float tempv[8], s1 = 0.f, s2 = 0.f;
    #pragma unroll
    for (int i = 0; i < 8; i++) {
        const int v = lane + 32 * i;
        const float x   = q[(size_t)b * Vn + v];
        const float vis = state[(size_t)b * SROW + v];
        float tv = __expf(x - g_colM[v]) / g_colS[v] + 0.01f;
        tv = (vis == 0.0f) ? tv : 0.0f;    // masked terms exact zeros
        tempv[i] = tv;
        s1 += tv;
        s2 += x * Wv[v];
    }
    #pragma unroll
    for (int off = 16; off >= 1; off >>= 1) {
        s1 += __shfl_xor_sync(0xffffffffu, s1, off);
        s2 += __shfl_xor_sync(0xffffffffu, s2, off);
    }
    if (lane == 0) value[b] = s2 + bv[0];

    const float rowsum = s1;
    #pragma unroll
    for (int i = 0; i < 8; i++) {
        const int v = lane + 32 * i;
        float pol;
        if (rowsum == 0.0f) pol = (v == 0) ? 1.0f : 0.0f;
        else                pol = tempv[i] / rowsum;
        policy[(size_t)b * Vn + v] = pol;
    }
}

// ---------------------------------------------------------------- launch
extern "C" void kernel_launch(void* const* d_in, const int* in_sizes, int n_in,
                              void* d_out, int out_size)
{
    const float* state = (const float*)d_in[0];
    const float* W1    = (const float*)d_in[1];
    const float* b_vis = (const float*)d_in[2];
    const float* w2    = (const float*)d_in[3];
    const float* Wv    = (const float*)d_in[4];
    const float* bv    = (const float*)d_in[5];

    float* out    = (float*)d_out;
    float* q      = out;
    float* policy = out + (size_t)Bn * Vn;
    float* value  = out + (size_t)2 * Bn * Vn;

    int nsm = 148;
    cudaDeviceGetAttribute(&nsm, cudaDevAttrMultiProcessorCount, 0);
    if (nsm <= 0 || nsm > Bn) nsm = 148;

    cudaFuncSetAttribute(k1_gemm, cudaFuncAttributeMaxDynamicSharedMemorySize,
                         SMEM_BYTES);

    k1_gemm<<<nsm, NTH, SMEM_BYTES>>>(state, W1, b_vis, w2, q);
    k2_colpart<<<64, 256>>>(q);
    k2_colcomb<<<1, 256>>>();
    k3_final<<<Bn / 8, 256>>>(q, state, Wv, bv, policy, value);
}

// round 14
// speedup vs baseline: 1.3411x; 1.0702x over previous
#include <cuda_runtime.h>
#include <cuda_fp16.h>
#include <cstdint>

// ---------------------------------------------------------------- constants
#define Bn 4096
#define Vn 256
#define Hn 64
#define SROW (257 * 256)        // floats per batch element of `state`

#define NTH  256                // 8 warps
#define NSTG 4                  // A pipeline stages
#define NCHK 8                  // 8 chunks of 32 k per block (block = 1 batch)

#define ASTRIDE 40              // A row stride (G*8+2t distinct per 16-lane phase)
#define BPITCH  264             // B fp16 [n][k] pitch in halves (4g+t distinct banks)
#define ASTF (256 * ASTRIDE)    // floats per A stage (10240 = 40KB)

// smem: A[4][10240] f32 + B 64x264 f16 (8448 f32-equiv) + bias 64 + w2 64
#define SMEM_FLOATS (NSTG * ASTF + 8448 + 128)
#define SMEM_BYTES  (SMEM_FLOATS * 4)   // 198144

// ---------------------------------------------------------------- scratch
__device__ float g_pm[64 * Vn];
__device__ float g_ps[64 * Vn];
__device__ float g_colM[Vn];
__device__ float g_colS[Vn];

// ---------------------------------------------------------------- helpers
__device__ __forceinline__ uint32_t smem_u32(const void* p) {
    uint32_t a;
    asm("{ .reg .u64 t; cvta.to.shared.u64 t, %1; cvt.u32.u64 %0, t; }"
        : "=r"(a) : "l"(p));
    return a;
}
__device__ __forceinline__ void cpa16(uint32_t dst, const void* src) {
    asm volatile("cp.async.cg.shared.global [%0], [%1], 16;" :: "r"(dst), "l"(src));
}
#define CPA_COMMIT() asm volatile("cp.async.commit_group;" ::: "memory")

__device__ __forceinline__ uint32_t packh2(float x, float y) {
    const __half2 h = __floats2half2_rn(x, y);   // x -> low half
    return *(const uint32_t*)&h;
}
__device__ __forceinline__ void mma_f16(float* d, const uint32_t* a,
                                        uint32_t b0, uint32_t b1) {
    asm volatile(
        "mma.sync.aligned.m16n8k16.row.col.f32.f16.f16.f32 "
        "{%0,%1,%2,%3}, {%4,%5,%6,%7}, {%8,%9}, {%0,%1,%2,%3};"
        : "+f"(d[0]), "+f"(d[1]), "+f"(d[2]), "+f"(d[3])
        : "r"(a[0]), "r"(a[1]), "r"(a[2]), "r"(a[3]), "r"(b0), "r"(b1));
}

// issue one 256-row x 32-k A chunk into stage `stg` via cp.async (one group)
__device__ __forceinline__ void issue_chunk(const float* __restrict__ state,
                                            uint32_t sA_u32, int blk, int c,
                                            int stg, int tid) {
    const int kv = tid & 7;         // 16B granule within 32-float k-chunk
    const int r0 = tid >> 3;        // 0..31 base row
    const float* src = state + (size_t)blk * SROW + (size_t)(r0 + 1) * 256
                     + c * 32 + kv * 4;
    uint32_t dst = sA_u32 + (uint32_t)(stg * ASTF + r0 * ASTRIDE + kv * 4) * 4u;
    #pragma unroll
    for (int i = 0; i < 8; i++) {   // rows r0 + 32*i
        cpa16(dst, src);
        dst += 32 * ASTRIDE * 4;
        src += 32 * 256;
    }
    CPA_COMMIT();
}

// ---------------------------------------------------------------- K1
// q[b*256+v] = sum_h relu( dist[b,v,:].W1[:,h] + vis[b,v]*b_vis[h] ) * w2[h]
// Persistent CTA; block = one batch (256 rows). Warp tile 32 rows x 64 h.
// fp16 m16n8k16 MMA, fp32 accumulate. 3 chunks in flight (4 stages).
__global__ __launch_bounds__(NTH, 1)
void k1_gemm(const float* __restrict__ state, const float* __restrict__ W1,
             const float* __restrict__ b_vis, const float* __restrict__ w2,
             float* __restrict__ qout)
{
    extern __shared__ __align__(16) float sm[];
    float*  sA    = sm;
    __half* sB16  = (__half*)(sm + NSTG * ASTF);      // [64][BPITCH] halves
    float*  sBias = sm + NSTG * ASTF + 8448;
    float*  sW2   = sBias + 64;
    const uint32_t sA_u32 = smem_u32(sA);

    const int tid  = threadIdx.x;
    const int lane = tid & 31;
    const int warp = tid >> 5;
    const int bx   = blockIdx.x;
    const int G    = gridDim.x;

    const int nblk = (Bn - bx + G - 1) / G;
    const int NCC  = nblk * NCHK;   // >= 8 chunks always (nblk >= 1)

    // prologue: issue chunk 0, stage B, then chunks 1 and 2
    issue_chunk(state, sA_u32, bx, 0, 0, tid);

    // stage B = W1 [256 k][64 h] -> fp16 transposed [h][k], pitch 264
    #pragma unroll
    for (int i = 0; i < 16; i++) {
        const int idx  = tid + 256 * i;      // float4 index 0..4095 over W1
        const int kr   = idx >> 4;           // k row
        const int quad = idx & 15;           // h group of 4
        const float4 v = ((const float4*)W1)[idx];
        __half* dst = sB16 + (quad * 4) * BPITCH + kr;
        dst[0]          = __float2half_rn(v.x);
        dst[BPITCH]     = __float2half_rn(v.y);
        dst[2 * BPITCH] = __float2half_rn(v.z);
        dst[3 * BPITCH] = __float2half_rn(v.w);
    }
    if (tid < 64)        sBias[tid]    = b_vis[tid];
    else if (tid < 128)  sW2[tid - 64] = w2[tid - 64];

    if (1 < NCC) issue_chunk(state, sA_u32, bx + (1 >> 3) * G, 1 & 7, 1, tid);
    if (2 < NCC) issue_chunk(state, sA_u32, bx + (2 >> 3) * G, 2 & 7, 2, tid);
    __syncthreads();   // B + bias visible to all

    const int gq = lane >> 2;       // groupID 0..7
    const int t2 = (lane & 3) * 2;

    float d[2][8][4];

    for (int cc = 0; cc < NCC; cc++) {
        const int blk = bx + (cc >> 3) * G;
        const int c   = cc & 7;

        // wait for group cc: groups issued after it so far = min(NCC-1-cc, 2)
        const int after = NCC - 1 - cc;
        if (after >= 2)      asm volatile("cp.async.wait_group 2;" ::: "memory");
        else if (after == 1) asm volatile("cp.async.wait_group 1;" ::: "memory");
        else                 asm volatile("cp.async.wait_group 0;" ::: "memory");
        // barrier: (a) makes chunk cc visible to all threads, (b) orders
        // compute(cc-1) before the overwrite of stage (cc+3)%4 below.
        __syncthreads();

        if (cc + 3 < NCC) {
            const int cn = cc + 3;
            issue_chunk(state, sA_u32, bx + (cn >> 3) * G, cn & 7, cn & 3, tid);
        }

        if (c == 0) {
            #pragma unroll
            for (int g = 0; g < 2; g++)
                #pragma unroll
                for (int j = 0; j < 8; j++)
                    #pragma unroll
                    for (int e = 0; e < 4; e++) d[g][j][e] = 0.f;
        }

        const float* As = sA + (cc & 3) * ASTF;
        #pragma unroll
        for (int ks = 0; ks < 2; ks++) {
            const int k0 = ks * 16;
            const int kg = c * 32 + k0;

            uint32_t a[2][4];
            #pragma unroll
            for (int g = 0; g < 2; g++) {
                const float* ap = As + (warp * 32 + g * 16 + gq) * ASTRIDE
                                + k0 + t2;
                const float2 v0 = *(const float2*)(ap);
                const float2 v1 = *(const float2*)(ap + 8 * ASTRIDE);
                const float2 v2 = *(const float2*)(ap + 8);
                const float2 v3 = *(const float2*)(ap + 8 * ASTRIDE + 8);
                a[g][0] = packh2(v0.x, v0.y);
                a[g][1] = packh2(v1.x, v1.y);
                a[g][2] = packh2(v2.x, v2.y);
                a[g][3] = packh2(v3.x, v3.y);
            }
            #pragma unroll
            for (int j = 0; j < 8; j++) {
                const __half* bp = sB16 + (j * 8 + gq) * BPITCH + kg + t2;
                const uint32_t b0 = *(const uint32_t*)(bp);
                const uint32_t b1 = *(const uint32_t*)(bp + 8);
                mma_f16(d[0][j], a[0], b0, b1);
                mma_f16(d[1][j], a[1], b0, b1);
            }
        }

        if (c == 7) {
            // fused epilogue: relu(acc + vis*bias)*w2, reduce over h
            #pragma unroll
            for (int g = 0; g < 2; g++) {
                #pragma unroll
                for (int half = 0; half < 2; half++) {
                    const int r = warp * 32 + g * 16 + gq + half * 8;
                    const float vis = __ldg(state + (size_t)blk * SROW + r);
                    float p = 0.f;
                    #pragma unroll
                    for (int j = 0; j < 8; j++) {
                        const int n = j * 8 + t2;
                        p += fmaxf(fmaf(vis, sBias[n],     d[g][j][half * 2]),     0.f) * sW2[n];
                        p += fmaxf(fmaf(vis, sBias[n + 1], d[g][j][half * 2 + 1]), 0.f) * sW2[n + 1];
                    }
                    p += __shfl_xor_sync(0xffffffffu, p, 1);
                    p += __shfl_xor_sync(0xffffffffu, p, 2);
                    if ((lane & 3) == 0)
                        qout[(size_t)blk * 256 + r] = p;
                }
            }
        }
    }
}

// ---------------------------------------------------------------- K2: column softmax stats
__global__ __launch_bounds__(256) void k2_colpart(const float* __restrict__ q)
{
    const int t  = threadIdx.x;
    const int r0 = blockIdx.x * 64;
    float m = -3.402823466e38f, s = 0.f;
    const float* p = q + (size_t)r0 * Vn + t;
    #pragma unroll 4
    for (int i = 0; i < 64; i++) {
        const float x  = p[(size_t)i * Vn];
        const float nm = fmaxf(m, x);
        s = s * __expf(m - nm) + __expf(x - nm);
        m = nm;
    }
    g_pm[blockIdx.x * Vn + t] = m;
    g_ps[blockIdx.x * Vn + t] = s;
}

__global__ __launch_bounds__(256) void k2_colcomb()
{
    const int t = threadIdx.x;
    float M = -3.402823466e38f;
    #pragma unroll 8
    for (int i = 0; i < 64; i++) M = fmaxf(M, g_pm[i * Vn + t]);
    float S = 0.f;
    #pragma unroll 8
    for (int i = 0; i < 64; i++) S += g_ps[i * Vn + t] * __expf(g_pm[i * Vn + t] - M);
    g_colM[t] = M;
    g_colS[t] = S;
}

// ---------------------------------------------------------------- K3: policy + value
// warp-per-batch: no smem, no block syncs. 8 warps/block, grid = Bn/8.
__global__ __launch_bounds__(256) void k3_final(
    const float* __restrict__ q, const float* __restrict__ state,
    const float* __restrict__ Wv, const float* __restrict__ bv,
    float* __restrict__ policy, float* __restrict__ value)
{
    const int lane = threadIdx.x & 31;
    const int b    = blockIdx.x * 8 + (threadIdx.x >> 5);

    float tempv[8], s1 = 0.f, s2 = 0.f;
    #pragma unroll
    for (int i = 0; i < 8; i++) {
        const int v = lane + 32 * i;
        const float x   = q[(size_t)b * Vn + v];
        const float vis = state[(size_t)b * SROW + v];
        float tv = __expf(x - g_colM[v]) / g_colS[v] + 0.01f;
        tv = (vis == 0.0f) ? tv : 0.0f;    // masked terms exact zeros
        tempv[i] = tv;
        s1 += tv;
        s2 += x * Wv[v];
    }
    #pragma unroll
    for (int off = 16; off >= 1; off >>= 1) {
        s1 += __shfl_xor_sync(0xffffffffu, s1, off);
        s2 += __shfl_xor_sync(0xffffffffu, s2, off);
    }
    if (lane == 0) value[b] = s2 + bv[0];

    const float rowsum = s1;
    #pragma unroll
    for (int i = 0; i < 8; i++) {
        const int v = lane + 32 * i;
        float pol;
        if (rowsum == 0.0f) pol = (v == 0) ? 1.0f : 0.0f;
        else                pol = tempv[i] / rowsum;
        policy[(size_t)b * Vn + v] = pol;
    }
}

// ---------------------------------------------------------------- launch
extern "C" void kernel_launch(void* const* d_in, const int* in_sizes, int n_in,
                              void* d_out, int out_size)
{
    const float* state = (const float*)d_in[0];
    const float* W1    = (const float*)d_in[1];
    const float* b_vis = (const float*)d_in[2];
    const float* w2    = (const float*)d_in[3];
    const float* Wv    = (const float*)d_in[4];
    const float* bv    = (const float*)d_in[5];

    float* out    = (float*)d_out;
    float* q      = out;
    float* policy = out + (size_t)Bn * Vn;
    float* value  = out + (size_t)2 * Bn * Vn;

    int nsm = 148;
    cudaDeviceGetAttribute(&nsm, cudaDevAttrMultiProcessorCount, 0);
    if (nsm <= 0 || nsm > Bn) nsm = 148;

    cudaFuncSetAttribute(k1_gemm, cudaFuncAttributeMaxDynamicSharedMemorySize,
                         SMEM_BYTES);

    k1_gemm<<<nsm, NTH, SMEM_BYTES>>>(state, W1, b_vis, w2, q);
    k2_colpart<<<64, 256>>>(q);
    k2_colcomb<<<1, 256>>>();
    k3_final<<<Bn / 8, 256>>>(q, state, Wv, bv, policy, value);
}